// round 6
// baseline (speedup 1.0000x reference)
#include <cuda_runtime.h>
#include <cuda_bf16.h>
#include <math.h>
#include <stdint.h>

// ---------------------------------------------------------------------------
// VisLSTM, tf32 tensor cores, sm_103a.
//  - all GEMM operands pre-rounded to tf32 (no cvt in inner loops)
//  - W_ih/W_hh gate-interleaved so the LSTM cell fuses into the recurrent
//    GEMM epilogue (no HW buffer, no separate cell kernel)
//  - h double-buffered across the 49 steps
// ---------------------------------------------------------------------------

#define NB    512
#define TT    48
#define SEQ   49
#define EMBD  1024
#define HID   1024
#define G4    4096
#define IMGD  4096
#define VOC   32000

// Scratch (static device globals; allocation-free per harness rules)
__device__ float g_X    [(size_t)SEQ * NB * EMBD];   // rounded
__device__ float g_GX   [(size_t)SEQ * NB * G4];     // fp32, gate-interleaved cols
__device__ float g_EI   [(size_t)NB * HID];          // rounded
__device__ float g_hA   [(size_t)NB * HID];          // rounded h ping
__device__ float g_hB   [(size_t)NB * HID];          // rounded h pong
__device__ float g_c    [(size_t)NB * HID];
__device__ float g_IFr  [(size_t)NB * IMGD];         // rounded img_feat
__device__ float g_Wimgr[(size_t)HID * IMGD];        // rounded W_img
__device__ float g_Wihp [(size_t)G4 * EMBD];         // rounded + permuted W_ih
__device__ float g_Whhp [(size_t)G4 * HID];          // rounded + permuted W_hh
__device__ float g_Woutr[(size_t)VOC * HID];         // rounded W_out
__device__ float g_biasp[G4];                        // permuted b_ih + b_hh

// ---------------------------------------------------------------------------
// helpers
// ---------------------------------------------------------------------------
__device__ __forceinline__ void cp16(void* s, const void* g) {
    uint32_t sa = (uint32_t)__cvta_generic_to_shared(s);
    asm volatile("cp.async.cg.shared.global [%0], [%1], 16;" :: "r"(sa), "l"(g));
}
__device__ __forceinline__ float rtf(float x) {
    uint32_t r;
    asm("cvt.rna.tf32.f32 %0, %1;" : "=r"(r) : "f"(x));
    return __uint_as_float(r);
}
__device__ __forceinline__ void mma_tf32(float* c, const uint32_t* a, const uint32_t* b) {
    asm volatile(
        "mma.sync.aligned.m16n8k8.row.col.f32.tf32.tf32.f32 "
        "{%0,%1,%2,%3}, {%4,%5,%6,%7}, {%8,%9}, {%0,%1,%2,%3};"
        : "+f"(c[0]), "+f"(c[1]), "+f"(c[2]), "+f"(c[3])
        : "r"(a[0]), "r"(a[1]), "r"(a[2]), "r"(a[3]), "r"(b[0]), "r"(b[1]));
}
__device__ __forceinline__ float sigm(float x) { return 1.f / (1.f + expf(-x)); }

// ---------------------------------------------------------------------------
// prep kernels
// ---------------------------------------------------------------------------
__global__ void round_copy(float* __restrict__ dst, const float* __restrict__ src, int n4)
{
    int i = blockIdx.x * blockDim.x + threadIdx.x;
    if (i >= n4) return;
    float4 v = reinterpret_cast<const float4*>(src)[i];
    v.x = rtf(v.x); v.y = rtf(v.y); v.z = rtf(v.z); v.w = rtf(v.w);
    reinterpret_cast<float4*>(dst)[i] = v;
}

// permute rows of W[4096][K] to gate-interleaved: new_row = 4*(r%1024) + r/1024
__global__ void permute_round_w(float* __restrict__ dst, const float* __restrict__ src, int K)
{
    const int r  = blockIdx.x;                 // 0..4095
    const int nr = ((r & 1023) << 2) + (r >> 10);
    const float* s = src + (size_t)r * K;
    float*       d = dst + (size_t)nr * K;
    for (int c4 = threadIdx.x; c4 < (K >> 2); c4 += blockDim.x) {
        float4 v = reinterpret_cast<const float4*>(s)[c4];
        v.x = rtf(v.x); v.y = rtf(v.y); v.z = rtf(v.z); v.w = rtf(v.w);
        reinterpret_cast<float4*>(d)[c4] = v;
    }
}

__global__ void bias_perm(float* __restrict__ dst, const float* __restrict__ b1,
                          const float* __restrict__ b2)
{
    int r = blockIdx.x * blockDim.x + threadIdx.x;   // 0..4095
    int nr = ((r & 1023) << 2) + (r >> 10);
    dst[nr] = b1[r] + b2[r];
}

__global__ void zero_hc(float* __restrict__ h, float* __restrict__ c)
{
    int i = blockIdx.x * blockDim.x + threadIdx.x;
    h[i] = 0.f;
    c[i] = 0.f;
}

__global__ void assemble_X(const int* __restrict__ questions,
                           const float* __restrict__ emb,
                           const float* __restrict__ EI,
                           const int* __restrict__ first_words,
                           float* __restrict__ X)
{
    const int slot = blockIdx.x;
    const int n    = blockIdx.y;
    const int fw   = (*first_words) != 0;
    const int img_slot = fw ? 0 : TT;

    const float* src;
    if (slot == img_slot) {
        src = EI + (size_t)n * HID;
    } else {
        const int t = fw ? (slot - 1) : slot;
        const int q = questions[n * TT + t];
        src = emb + (size_t)q * EMBD;
    }
    float4 v = reinterpret_cast<const float4*>(src)[threadIdx.x];
    v.x = rtf(v.x); v.y = rtf(v.y); v.z = rtf(v.z); v.w = rtf(v.w);
    reinterpret_cast<float4*>(X + ((size_t)slot * NB + n) * EMBD)[threadIdx.x] = v;
}

// ---------------------------------------------------------------------------
// Generic TF32 GEMM (operands pre-rounded): C = A[M,K] @ B[N,K]^T + bias
// M%128==0, N%128==0, K%16==0. 128x128 tile, BK=16 double-buffered, 8 warps.
// ---------------------------------------------------------------------------
template <bool ROUND_OUT>
__global__ __launch_bounds__(256, 2)
void tf32_gemm_pre(const float* __restrict__ A, const float* __restrict__ B,
                   const float* __restrict__ bias, float* __restrict__ C,
                   int M, int N, int K)
{
    __shared__ float As[2][128][20];
    __shared__ float Bs[2][128][20];

    const int tid  = threadIdx.x;
    const int wid  = tid >> 5;
    const int lane = tid & 31;
    const int brow = blockIdx.y * 128;
    const int bcol = blockIdx.x * 128;
    const int wm = (wid & 1) * 64;
    const int wn = (wid >> 1) * 32;

    const float* Abase = A + (size_t)brow * K;
    const float* Bbase = B + (size_t)bcol * K;

    float acc[4][4][4];
    #pragma unroll
    for (int mt = 0; mt < 4; mt++)
        #pragma unroll
        for (int nt = 0; nt < 4; nt++)
            #pragma unroll
            for (int r = 0; r < 4; r++) acc[mt][nt][r] = 0.f;

    const int ntiles = K >> 4;

    #pragma unroll
    for (int i = 0; i < 2; i++) {
        int idx = tid + i * 256;
        int r = idx >> 2, cg = (idx & 3) * 4;
        cp16(&As[0][r][cg], Abase + (size_t)r * K + cg);
        cp16(&Bs[0][r][cg], Bbase + (size_t)r * K + cg);
    }
    asm volatile("cp.async.commit_group;");

    const int r0 = lane >> 2;
    const int c0 = lane & 3;

    for (int kt = 0; kt < ntiles; kt++) {
        const int buf = kt & 1;
        if (kt + 1 < ntiles) {
            const int nb_ = buf ^ 1;
            const int koff = (kt + 1) << 4;
            #pragma unroll
            for (int i = 0; i < 2; i++) {
                int idx = tid + i * 256;
                int r = idx >> 2, cg = (idx & 3) * 4;
                cp16(&As[nb_][r][cg], Abase + (size_t)r * K + koff + cg);
                cp16(&Bs[nb_][r][cg], Bbase + (size_t)r * K + koff + cg);
            }
            asm volatile("cp.async.commit_group;");
            asm volatile("cp.async.wait_group 1;");
        } else {
            asm volatile("cp.async.wait_group 0;");
        }
        __syncthreads();

        #pragma unroll
        for (int kk = 0; kk < 16; kk += 8) {
            uint32_t afr[4][4];
            uint32_t bfr[4][2];
            #pragma unroll
            for (int mt = 0; mt < 4; mt++) {
                const int rb = wm + mt * 16;
                afr[mt][0] = __float_as_uint(As[buf][rb + r0][kk + c0]);
                afr[mt][1] = __float_as_uint(As[buf][rb + r0 + 8][kk + c0]);
                afr[mt][2] = __float_as_uint(As[buf][rb + r0][kk + c0 + 4]);
                afr[mt][3] = __float_as_uint(As[buf][rb + r0 + 8][kk + c0 + 4]);
            }
            #pragma unroll
            for (int nt = 0; nt < 4; nt++) {
                const int nb2 = wn + nt * 8;
                bfr[nt][0] = __float_as_uint(Bs[buf][nb2 + r0][kk + c0]);
                bfr[nt][1] = __float_as_uint(Bs[buf][nb2 + r0][kk + c0 + 4]);
            }
            #pragma unroll
            for (int mt = 0; mt < 4; mt++)
                #pragma unroll
                for (int nt = 0; nt < 4; nt++)
                    mma_tf32(acc[mt][nt], afr[mt], bfr[nt]);
        }
        __syncthreads();
    }

    #pragma unroll
    for (int mt = 0; mt < 4; mt++) {
        #pragma unroll
        for (int nt = 0; nt < 4; nt++) {
            const int row = brow + wm + mt * 16 + r0;
            const int col = bcol + wn + nt * 8 + 2 * c0;
            float bv0 = bias ? bias[col]     : 0.f;
            float bv1 = bias ? bias[col + 1] : 0.f;
            float o0 = acc[mt][nt][0] + bv0, o1 = acc[mt][nt][1] + bv1;
            float o2 = acc[mt][nt][2] + bv0, o3 = acc[mt][nt][3] + bv1;
            if (ROUND_OUT) { o0 = rtf(o0); o1 = rtf(o1); o2 = rtf(o2); o3 = rtf(o3); }
            *reinterpret_cast<float2*>(C + (size_t)row * N + col)       = make_float2(o0, o1);
            *reinterpret_cast<float2*>(C + (size_t)(row + 8) * N + col) = make_float2(o2, o3);
        }
    }
}

// ---------------------------------------------------------------------------
// Fused LSTM step: HW = h_in @ Whh_p^T (tf32 MMA), then cell epilogue:
//   gates = HW + GX_t (gate-interleaved cols), c/h update, hs write.
// Grid (G4/128, NB/128) = (32, 4). h double-buffered by caller.
// ---------------------------------------------------------------------------
__global__ __launch_bounds__(256)
void lstm_step(const float* __restrict__ h_in, const float* __restrict__ Whh,
               const float* __restrict__ GX_t, float* __restrict__ c,
               float* __restrict__ h_out, float* __restrict__ hs_out, int t)
{
    __shared__ union {
        struct { float As[2][128][20]; float Bs[2][128][20]; } ab;
        float cs[64 * 132];
    } sm;

    const int tid  = threadIdx.x;
    const int wid  = tid >> 5;
    const int lane = tid & 31;
    const int brow = blockIdx.y * 128;        // batch rows
    const int bcol = blockIdx.x * 128;        // gate cols (interleaved)
    const int wm = (wid & 1) * 64;
    const int wn = (wid >> 1) * 32;

    const float* Abase = h_in + (size_t)brow * HID;
    const float* Bbase = Whh  + (size_t)bcol * HID;

    float acc[4][4][4];
    #pragma unroll
    for (int mt = 0; mt < 4; mt++)
        #pragma unroll
        for (int nt = 0; nt < 4; nt++)
            #pragma unroll
            for (int r = 0; r < 4; r++) acc[mt][nt][r] = 0.f;

    const int ntiles = HID >> 4;   // 64

    #pragma unroll
    for (int i = 0; i < 2; i++) {
        int idx = tid + i * 256;
        int r = idx >> 2, cg = (idx & 3) * 4;
        cp16(&sm.ab.As[0][r][cg], Abase + (size_t)r * HID + cg);
        cp16(&sm.ab.Bs[0][r][cg], Bbase + (size_t)r * HID + cg);
    }
    asm volatile("cp.async.commit_group;");

    const int r0 = lane >> 2;
    const int c0 = lane & 3;

    for (int kt = 0; kt < ntiles; kt++) {
        const int buf = kt & 1;
        if (kt + 1 < ntiles) {
            const int nb_ = buf ^ 1;
            const int koff = (kt + 1) << 4;
            #pragma unroll
            for (int i = 0; i < 2; i++) {
                int idx = tid + i * 256;
                int r = idx >> 2, cg = (idx & 3) * 4;
                cp16(&sm.ab.As[nb_][r][cg], Abase + (size_t)r * HID + koff + cg);
                cp16(&sm.ab.Bs[nb_][r][cg], Bbase + (size_t)r * HID + koff + cg);
            }
            asm volatile("cp.async.commit_group;");
            asm volatile("cp.async.wait_group 1;");
        } else {
            asm volatile("cp.async.wait_group 0;");
        }
        __syncthreads();

        #pragma unroll
        for (int kk = 0; kk < 16; kk += 8) {
            uint32_t afr[4][4];
            uint32_t bfr[4][2];
            #pragma unroll
            for (int mt = 0; mt < 4; mt++) {
                const int rb = wm + mt * 16;
                afr[mt][0] = __float_as_uint(sm.ab.As[buf][rb + r0][kk + c0]);
                afr[mt][1] = __float_as_uint(sm.ab.As[buf][rb + r0 + 8][kk + c0]);
                afr[mt][2] = __float_as_uint(sm.ab.As[buf][rb + r0][kk + c0 + 4]);
                afr[mt][3] = __float_as_uint(sm.ab.As[buf][rb + r0 + 8][kk + c0 + 4]);
            }
            #pragma unroll
            for (int nt = 0; nt < 4; nt++) {
                const int nb2 = wn + nt * 8;
                bfr[nt][0] = __float_as_uint(sm.ab.Bs[buf][nb2 + r0][kk + c0]);
                bfr[nt][1] = __float_as_uint(sm.ab.Bs[buf][nb2 + r0][kk + c0 + 4]);
            }
            #pragma unroll
            for (int mt = 0; mt < 4; mt++)
                #pragma unroll
                for (int nt = 0; nt < 4; nt++)
                    mma_tf32(acc[mt][nt], afr[mt], bfr[nt]);
        }
        __syncthreads();
    }

    // ---- fused cell epilogue: two 64-row phases through sm.cs ----
    #pragma unroll
    for (int p = 0; p < 2; p++) {
        if ((wid & 1) == p) {
            #pragma unroll
            for (int mt = 0; mt < 4; mt++)
                #pragma unroll
                for (int nt = 0; nt < 4; nt++) {
                    const int rl  = mt * 16 + r0;            // 0..63
                    const int col = wn + nt * 8 + 2 * c0;
                    sm.cs[rl * 132 + col]           = acc[mt][nt][0];
                    sm.cs[rl * 132 + col + 1]       = acc[mt][nt][1];
                    sm.cs[(rl + 8) * 132 + col]     = acc[mt][nt][2];
                    sm.cs[(rl + 8) * 132 + col + 1] = acc[mt][nt][3];
                }
        }
        __syncthreads();

        #pragma unroll
        for (int w = 0; w < 8; w++) {
            const int item = w * 256 + tid;        // 0..2047
            const int nl = item >> 5;              // 0..63
            const int j  = item & 31;              // unit within tile
            const int ng = brow + p * 64 + nl;     // global batch row
            const int u  = (bcol >> 2) + j;        // global hidden unit

            float4 hw = *reinterpret_cast<float4*>(&sm.cs[nl * 132 + 4 * j]);
            float4 gx = *reinterpret_cast<const float4*>(
                            GX_t + (size_t)ng * G4 + bcol + 4 * j);

            const float i_ = sigm(hw.x + gx.x);
            const float f_ = sigm(hw.y + gx.y);
            const float g_ = tanhf(hw.z + gx.z);
            const float o_ = sigm(hw.w + gx.w);

            const size_t ci = (size_t)ng * HID + u;
            const float cc = f_ * c[ci] + i_ * g_;
            const float hh = o_ * tanhf(cc);
            c[ci] = cc;
            h_out[ci] = rtf(hh);
            hs_out[((size_t)ng * SEQ + t) * HID + u] = hh;
        }
        __syncthreads();
    }
}

// ---------------------------------------------------------------------------
// Launch
// ---------------------------------------------------------------------------
extern "C" void kernel_launch(void* const* d_in, const int* in_sizes, int n_in,
                              void* d_out, int out_size)
{
    const int*   questions = (const int*)  d_in[0];
    const float* img_feat  = (const float*)d_in[1];
    const float* emb       = (const float*)d_in[2];
    const float* W_img     = (const float*)d_in[3];
    const float* b_img     = (const float*)d_in[4];
    const float* W_ih      = (const float*)d_in[5];
    const float* W_hh      = (const float*)d_in[6];
    const float* b_ih      = (const float*)d_in[7];
    const float* b_hh      = (const float*)d_in[8];
    const float* W_out     = (const float*)d_in[9];
    const float* b_out     = (const float*)d_in[10];
    const int*   first_w   = (const int*)  d_in[11];

    float* out    = (float*)d_out;             // [512,32000]
    float* hs_out = out + (size_t)NB * VOC;    // [512,49,1024]

    float *X, *GX, *EI, *hA, *hB, *c, *IFr, *Wimgr, *Wihp, *Whhp, *Woutr, *biasp;
    cudaGetSymbolAddress((void**)&X,     g_X);
    cudaGetSymbolAddress((void**)&GX,    g_GX);
    cudaGetSymbolAddress((void**)&EI,    g_EI);
    cudaGetSymbolAddress((void**)&hA,    g_hA);
    cudaGetSymbolAddress((void**)&hB,    g_hB);
    cudaGetSymbolAddress((void**)&c,     g_c);
    cudaGetSymbolAddress((void**)&IFr,   g_IFr);
    cudaGetSymbolAddress((void**)&Wimgr, g_Wimgr);
    cudaGetSymbolAddress((void**)&Wihp,  g_Wihp);
    cudaGetSymbolAddress((void**)&Whhp,  g_Whhp);
    cudaGetSymbolAddress((void**)&Woutr, g_Woutr);
    cudaGetSymbolAddress((void**)&biasp, g_biasp);

    // --- prep: round / permute all GEMM operands ---
    round_copy<<<(NB * IMGD / 4 + 255) / 256, 256>>>(IFr, img_feat, NB * IMGD / 4);
    round_copy<<<(HID * IMGD / 4 + 255) / 256, 256>>>(Wimgr, W_img, HID * IMGD / 4);
    round_copy<<<(VOC * HID / 4 + 255) / 256, 256>>>(Woutr, W_out, VOC * HID / 4);
    permute_round_w<<<G4, 256>>>(Wihp, W_ih, EMBD);
    permute_round_w<<<G4, 256>>>(Whhp, W_hh, HID);
    bias_perm<<<G4 / 256, 256>>>(biasp, b_ih, b_hh);

    // 1) EI = round(img_feat @ W_img^T + b_img)    (512 x 1024 x 4096)
    {
        dim3 grid(HID / 128, NB / 128);
        tf32_gemm_pre<true><<<grid, 256>>>(IFr, Wimgr, b_img, EI, NB, HID, IMGD);
    }

    // 2) assemble rounded sequence X
    {
        dim3 grid(SEQ, NB);
        assemble_X<<<grid, EMBD / 4>>>(questions, emb, EI, first_w, X);
    }

    // 3) GX = X @ Wih_p^T + bias_p (gate-interleaved)   (25088 x 4096 x 1024)
    {
        dim3 grid(G4 / 128, (SEQ * NB) / 128);
        tf32_gemm_pre<false><<<grid, 256>>>(X, Wihp, biasp, GX, SEQ * NB, G4, EMBD);
    }

    // 4) zero state
    zero_hc<<<(NB * HID) / 256, 256>>>(hA, c);

    // 5) fused recurrence (h ping-pong)
    float* hbuf[2] = { hA, hB };
    for (int t = 0; t < SEQ; t++) {
        dim3 grid(G4 / 128, NB / 128);
        lstm_step<<<grid, 256>>>(hbuf[t & 1], Whhp, GX + (size_t)t * NB * G4,
                                 c, hbuf[(t + 1) & 1], hs_out, t);
    }

    // 6) output = h_final @ W_out^T + b_out        (512 x 32000 x 1024)
    {
        dim3 grid(VOC / 128, NB / 128);
        tf32_gemm_pre<false><<<grid, 256>>>(hbuf[SEQ & 1], Woutr, b_out, out,
                                            NB, VOC, HID);
    }
}